// round 2
// baseline (speedup 1.0000x reference)
#include <cuda_runtime.h>

// ---------------------------------------------------------------------------
// ActorGCN: 2-layer GCN + two 105-way heads + gumbel softmax
// N=100000 nodes, E=1600000 edges, H=64, F_IN=14, heads 105+105
//
// Index inputs (edge_index, stem_idxs) may arrive as int32 (harness-converted)
// or int64. A device-side probe detects which; all consumers branch on the flag.
// ---------------------------------------------------------------------------

#define NN 100000
#define EE 1600000

__device__ float g_bufA[NN * 64];
__device__ float g_bufB[NN * 64];
__device__ int   g_ecnt[NN];
__device__ float g_dinv[NN];
__device__ float g_stem[NN];
__device__ int   g_off[NN + 1];
__device__ int   g_cur[NN];
__device__ int   g_srcs[EE];
__device__ int   g_csum[1024];
__device__ int   g_coff[1024];
__device__ int   g_is64;

// Detect whether the edge buffer holds int64 (odd 32-bit words all zero) or int32.
__global__ void k_probe(const int* __restrict__ ei32) {
    __shared__ int nonzero;
    if (threadIdx.x == 0) nonzero = 0;
    __syncthreads();
    for (int i = threadIdx.x; i < 1024; i += 256) {
        if (ei32[2 * i + 1] != 0) nonzero = 1;
    }
    __syncthreads();
    if (threadIdx.x == 0) g_is64 = nonzero ? 0 : 1;
}

__device__ __forceinline__ int idx_at(const void* p, long long i) {
    return g_is64 ? (int)((const long long*)p)[i] : ((const int*)p)[i];
}

__global__ void k_init(int n) {
    int i = blockIdx.x * blockDim.x + threadIdx.x;
    if (i < n) { g_ecnt[i] = 0; g_stem[i] = 0.f; }
}

__global__ void k_stem(const void* __restrict__ si, int s) {
    int i = blockIdx.x * blockDim.x + threadIdx.x;
    if (i < s) {
        int v = idx_at(si, i);
        if (v >= 0 && v < NN) g_stem[v] = 1.0f;
    }
}

__global__ void k_hist(const void* __restrict__ ei, int e) {
    int i = blockIdx.x * blockDim.x + threadIdx.x;
    if (i < e) {
        int d = idx_at(ei, (long long)e + i);
        if (d >= 0 && d < NN) atomicAdd(&g_ecnt[d], 1);
    }
}

__global__ void k_chunksum(int n) {
    int c = blockIdx.x * blockDim.x + threadIdx.x;   // 0..1023
    int ch = (n + 1023) >> 10;
    int beg = c * ch, end = min(n, beg + ch);
    int sum = 0;
    for (int i = beg; i < end; i++) sum += g_ecnt[i];
    g_csum[c] = sum;
}

__global__ void k_scan() {
    __shared__ int sh[1024];
    int t = threadIdx.x;
    int v = g_csum[t];
    sh[t] = v; __syncthreads();
    for (int off = 1; off < 1024; off <<= 1) {
        int add = (t >= off) ? sh[t - off] : 0;
        __syncthreads();
        sh[t] += add;
        __syncthreads();
    }
    g_coff[t] = sh[t] - v;  // exclusive
}

__global__ void k_offsets(int n, int e) {
    int c = blockIdx.x * blockDim.x + threadIdx.x;   // 0..1023
    int ch = (n + 1023) >> 10;
    int beg = c * ch, end = min(n, beg + ch);
    if (beg > n) beg = n;
    int run = g_coff[c];
    for (int i = beg; i < end; i++) {
        g_off[i] = run;
        g_cur[i] = run;
        int d = g_ecnt[i];
        g_dinv[i] = rsqrtf((float)(d + 1));   // +1 self-loop
        run += d;
    }
    if (c == 0) g_off[n] = e;
}

__global__ void k_scatter(const void* __restrict__ ei, int e) {
    int i = blockIdx.x * blockDim.x + threadIdx.x;
    if (i < e) {
        int s = idx_at(ei, i);
        int d = idx_at(ei, (long long)e + i);
        if (s >= 0 && s < NN && d >= 0 && d < NN) {
            int p = atomicAdd(&g_cur[d], 1);
            if (p >= 0 && p < EE) g_srcs[p] = s;
        }
    }
}

// xw1 = [x | stem] @ W1 (15 x 64), no bias yet
__global__ void k_xw1(const float* __restrict__ x, const float* __restrict__ W1, int n) {
    __shared__ float sW[15 * 64];
    __shared__ float sx[4][15];
    int tx = threadIdx.x, ty = threadIdx.y;
    int tid = ty * 64 + tx;
    for (int idx = tid; idx < 15 * 64; idx += 256) sW[idx] = W1[idx];
    int node = blockIdx.x * 4 + ty;
    if (tx < 15 && node < n) sx[ty][tx] = (tx < 14) ? x[node * 14 + tx] : g_stem[node];
    __syncthreads();
    if (node < n) {
        float acc = 0.f;
        #pragma unroll
        for (int k = 0; k < 15; k++) acc += sx[ty][k] * sW[k * 64 + tx];
        g_bufA[node * 64 + tx] = acc;
    }
}

// Pull aggregation: out[i] = relu(dinv[i]*(dinv[i]*xw[i] + sum_e dinv[src]*xw[src]) + b) * drop
// reads g_bufA, writes g_bufB. One warp per node, 2 features per lane.
__global__ void k_agg(const float* __restrict__ bias, const float* __restrict__ drop, int n) {
    int lane = threadIdx.x & 31;
    int node = blockIdx.x * 8 + (threadIdx.x >> 5);
    if (node >= n) return;
    const float* __restrict__ in = g_bufA;
    float di = g_dinv[node];
    float a0 = di * in[node * 64 + lane];
    float a1 = di * in[node * 64 + 32 + lane];
    int beg = g_off[node], end = g_off[node + 1];
    for (int base = beg; base < end; base += 32) {
        int m = min(32, end - base);
        int sIdx = (lane < m) ? g_srcs[base + lane] : 0;
        float w   = (lane < m) ? g_dinv[sIdx] : 0.f;
        for (int j = 0; j < m; j++) {
            int   sj = __shfl_sync(0xffffffffu, sIdx, j);
            float wj = __shfl_sync(0xffffffffu, w, j);
            a0 += wj * in[sj * 64 + lane];
            a1 += wj * in[sj * 64 + 32 + lane];
        }
    }
    float o0 = di * a0 + bias[lane];
    float o1 = di * a1 + bias[lane + 32];
    o0 = fmaxf(o0, 0.f) * drop[(size_t)node * 64 + lane];
    o1 = fmaxf(o1, 0.f) * drop[(size_t)node * 64 + 32 + lane];
    g_bufB[node * 64 + lane] = o0;
    g_bufB[node * 64 + 32 + lane] = o1;
}

// bufA = bufB @ W2 (64x64). 64 threads, BM=64 nodes, 8x8 microtile.
__global__ void k_gemm64(const float* __restrict__ W, int n) {
    __shared__ float Ash[64 * 65];
    __shared__ float Wsh[64 * 64];
    int tid = threadIdx.x;        // 64 threads
    int base = blockIdx.x * 64;
    for (int idx = tid; idx < 4096; idx += 64) Wsh[idx] = W[idx];
    for (int idx = tid; idx < 4096; idx += 64) {
        int nl = idx >> 6, k = idx & 63;
        int node = base + nl;
        Ash[nl * 65 + k] = (node < n) ? g_bufB[node * 64 + k] : 0.f;
    }
    __syncthreads();
    int tx = tid & 7, ty = tid >> 3;
    float acc[8][8];
    #pragma unroll
    for (int r = 0; r < 8; r++)
        #pragma unroll
        for (int c = 0; c < 8; c++) acc[r][c] = 0.f;
    #pragma unroll 4
    for (int k = 0; k < 64; k++) {
        float4 w0 = *(const float4*)&Wsh[k * 64 + tx * 8];
        float4 w1 = *(const float4*)&Wsh[k * 64 + tx * 8 + 4];
        #pragma unroll
        for (int r = 0; r < 8; r++) {
            float a = Ash[(ty * 8 + r) * 65 + k];
            acc[r][0] += a * w0.x; acc[r][1] += a * w0.y;
            acc[r][2] += a * w0.z; acc[r][3] += a * w0.w;
            acc[r][4] += a * w1.x; acc[r][5] += a * w1.y;
            acc[r][6] += a * w1.z; acc[r][7] += a * w1.w;
        }
    }
    #pragma unroll
    for (int r = 0; r < 8; r++) {
        int node = base + ty * 8 + r;
        if (node < n) {
            float4 o0 = make_float4(acc[r][0], acc[r][1], acc[r][2], acc[r][3]);
            float4 o1 = make_float4(acc[r][4], acc[r][5], acc[r][6], acc[r][7]);
            *(float4*)&g_bufA[node * 64 + tx * 8]     = o0;
            *(float4*)&g_bufA[node * 64 + tx * 8 + 4] = o1;
        }
    }
}

// Heads GEMM: logits[n, 0..209] = h2 @ [Wb|Ws] + [bb|bs], split writes.
// 112 threads, BM=64 nodes x BN=112 cols (grid.y = 2 col tiles), 8x8 microtile.
__global__ void k_heads(const float* __restrict__ Wb, const float* __restrict__ bbv,
                        const float* __restrict__ Wst, const float* __restrict__ bsv,
                        float* __restrict__ outB, float* __restrict__ outS, int n) {
    __shared__ float Ash[64 * 65];
    __shared__ float Wsh[64 * 112];
    int tid = threadIdx.x;        // 112 threads
    int base = blockIdx.x * 64;
    int cbase = blockIdx.y * 112;
    {
        int c = tid;
        int col = cbase + c;
        for (int k = 0; k < 64; k++) {
            float v = 0.f;
            if (col < 105)      v = Wb[k * 105 + col];
            else if (col < 210) v = Wst[k * 105 + col - 105];
            Wsh[k * 112 + c] = v;
        }
    }
    for (int idx = tid; idx < 4096; idx += 112) {
        int nl = idx >> 6, k = idx & 63;
        int node = base + nl;
        Ash[nl * 65 + k] = (node < n) ? g_bufB[node * 64 + k] : 0.f;
    }
    __syncthreads();
    int tx = tid % 14, ty = tid / 14;   // tx: col group (0..13), ty: node group (0..7)
    float acc[8][8];
    #pragma unroll
    for (int r = 0; r < 8; r++)
        #pragma unroll
        for (int c = 0; c < 8; c++) acc[r][c] = 0.f;
    #pragma unroll 4
    for (int k = 0; k < 64; k++) {
        float4 w0 = *(const float4*)&Wsh[k * 112 + tx * 8];
        float4 w1 = *(const float4*)&Wsh[k * 112 + tx * 8 + 4];
        #pragma unroll
        for (int r = 0; r < 8; r++) {
            float a = Ash[(ty * 8 + r) * 65 + k];
            acc[r][0] += a * w0.x; acc[r][1] += a * w0.y;
            acc[r][2] += a * w0.z; acc[r][3] += a * w0.w;
            acc[r][4] += a * w1.x; acc[r][5] += a * w1.y;
            acc[r][6] += a * w1.z; acc[r][7] += a * w1.w;
        }
    }
    #pragma unroll
    for (int r = 0; r < 8; r++) {
        int node = base + ty * 8 + r;
        if (node < n) {
            #pragma unroll
            for (int c2 = 0; c2 < 8; c2++) {
                int col = cbase + tx * 8 + c2;
                float v = acc[r][c2];
                if (col < 105)
                    outB[(size_t)node * 105 + col] = v + bbv[col];
                else if (col < 210)
                    outS[(size_t)node * 105 + col - 105] = v + bsv[col - 105];
            }
        }
    }
}

// Warp-per-row softmax over 105 entries of (logits + gumbel)
__global__ void k_softmax(const float* __restrict__ L, const float* __restrict__ G,
                          float* __restrict__ out, int n) {
    int w = blockIdx.x * 8 + (threadIdx.x >> 5);
    if (w >= n) return;
    int lane = threadIdx.x & 31;
    size_t o = (size_t)w * 105;
    float v0 = L[o + lane]      + G[o + lane];
    float v1 = L[o + lane + 32] + G[o + lane + 32];
    float v2 = L[o + lane + 64] + G[o + lane + 64];
    float v3 = (lane < 9) ? (L[o + lane + 96] + G[o + lane + 96]) : -1e30f;
    float m = fmaxf(fmaxf(v0, v1), fmaxf(v2, v3));
    #pragma unroll
    for (int off = 16; off; off >>= 1) m = fmaxf(m, __shfl_xor_sync(0xffffffffu, m, off));
    float e0 = __expf(v0 - m), e1 = __expf(v1 - m), e2 = __expf(v2 - m);
    float e3 = (lane < 9) ? __expf(v3 - m) : 0.f;
    float s = e0 + e1 + e2 + e3;
    #pragma unroll
    for (int off = 16; off; off >>= 1) s += __shfl_xor_sync(0xffffffffu, s, off);
    float inv = 1.0f / s;
    out[o + lane]      = e0 * inv;
    out[o + lane + 32] = e1 * inv;
    out[o + lane + 64] = e2 * inv;
    if (lane < 9) out[o + lane + 96] = e3 * inv;
}

extern "C" void kernel_launch(void* const* d_in, const int* in_sizes, int n_in,
                              void* d_out, int out_size) {
    const float* x   = (const float*)d_in[0];
    const float* W1  = (const float*)d_in[1];
    const float* b1  = (const float*)d_in[2];
    const float* W2  = (const float*)d_in[3];
    const float* b2  = (const float*)d_in[4];
    const float* Wb  = (const float*)d_in[5];
    const float* bb  = (const float*)d_in[6];
    const float* Ws  = (const float*)d_in[7];
    const float* bs  = (const float*)d_in[8];
    const float* dr1 = (const float*)d_in[9];
    const float* dr2 = (const float*)d_in[10];
    const float* gb  = (const float*)d_in[11];
    const float* gs  = (const float*)d_in[12];
    const void*  ei  = d_in[13];
    const void*  si  = d_in[14];

    int n = in_sizes[0] / 14;
    int e = in_sizes[13] / 2;
    int s = in_sizes[14];

    float* out = (float*)d_out;
    size_t NH = (size_t)n * 105;
    float* outB = out;
    float* outS = out + NH;
    float* selB = out + 2 * NH;
    float* selS = out + 3 * NH;

    k_probe   <<<1, 256>>>((const int*)ei);
    k_init    <<<(n + 255) / 256, 256>>>(n);
    k_stem    <<<(s + 255) / 256, 256>>>(si, s);
    k_hist    <<<(e + 255) / 256, 256>>>(ei, e);
    k_chunksum<<<4, 256>>>(n);
    k_scan    <<<1, 1024>>>();
    k_offsets <<<4, 256>>>(n, e);
    k_scatter <<<(e + 255) / 256, 256>>>(ei, e);
    k_xw1     <<<(n + 3) / 4, dim3(64, 4)>>>(x, W1, n);
    k_agg     <<<(n + 7) / 8, 256>>>(b1, dr1, n);
    k_gemm64  <<<(n + 63) / 64, 64>>>(W2, n);
    k_agg     <<<(n + 7) / 8, 256>>>(b2, dr2, n);
    k_heads   <<<dim3((n + 63) / 64, 2), 112>>>(Wb, bb, Ws, bs, outB, outS, n);
    k_softmax <<<(n + 7) / 8, 256>>>(outB, gb, selB, n);
    k_softmax <<<(n + 7) / 8, 256>>>(outS, gs, selS, n);
}